// round 17
// baseline (speedup 1.0000x reference)
#include <cuda_runtime.h>
#include <cuda_bf16.h>
#include <float.h>
#include <stdint.h>

#define B        16
#define H        320
#define W        320
#define HW       (H * W)
#define W4       (W / 4)     // 80
#define P        64
#define K_TOP    100
#define NBIN     256         // bins over (0.5, 1.0) by float-bit mantissa
#define SEGCAP   512         // per-(batch,bin) segment capacity
#define KEYCAP   1024        // selector smem key cap (> K_TOP + SEGCAP)
#define TR       20          // rows per block (H % TR == 0)
#define NBLK     (H / TR)    // 16 blocks per batch

// Output layout (float32, tuple order): coors | params | scores | mask
#define OFF_COORS  0
#define OFF_PARAMS 3200
#define OFF_SCORES 105600
#define OFF_MASK   107200

// Device scratch (zero-init at module load; selector resets -> replay safe)
__device__ unsigned           g_binc[B * NBIN];
__device__ unsigned           g_done[B];
__device__ unsigned long long g_seg[(size_t)B * NBIN * SEGCAP];

static __device__ __forceinline__ float fmax3(float a, float b, float c) {
    return fmaxf(fmaxf(a, b), c);
}
// bin 0..255 over score bits in [0x3F000000, 0x3F800000)
static __device__ __forceinline__ unsigned binOf(unsigned bits) {
    unsigned bn = (bits - 0x3F000000u) >> 15;
    return bn > (NBIN - 1u) ? (NBIN - 1u) : bn;
}

// Selection scratch overlays the NMS tile (tile is dead by selection time).
union SmemU {
    float tile[(TR + 2) * W];                    // 28160 B (NMS phase)
    struct {
        unsigned long long keys[KEYCAP];         // 8192 B
        float score[K_TOP];
        int   y[K_TOP];
        int   x[K_TOP];
        int   valid[K_TOP];
    } sel;
};

// ---------------------------------------------------------------------------
// Fused kernel. Grid (NBLK, B) = 256 blocks, 256 threads, single wave.
// ---------------------------------------------------------------------------
__global__ __launch_bounds__(256) void k_fused(const float* __restrict__ hms,
                                               const float* __restrict__ pms,
                                               float* __restrict__ out) {
    __shared__ SmemU u;
    __shared__ unsigned s_hist[NBIN];            // selection: clamped counts
    __shared__ unsigned s_pre[NBIN];             // selection: inclusive prefix
    __shared__ unsigned s_wsum[8];
    __shared__ unsigned s_ticket;
    __shared__ int s_c;

    const int b    = blockIdx.y;
    const int y0   = blockIdx.x * TR;
    const int tid  = threadIdx.x;
    const int lane = tid & 31;
    const int wid  = tid >> 5;
    const float* hb = hms + b * HW;

    // ---- Load (TR+2) rows as float4; OOB rows = -inf ----
    #pragma unroll
    for (int uu = 0; uu < 7; uu++) {
        int i = tid + uu * 256;
        if (i < (TR + 2) * W4) {
            int r  = i / W4;
            int gy = y0 - 1 + r;
            float4 v = make_float4(-FLT_MAX, -FLT_MAX, -FLT_MAX, -FLT_MAX);
            if (gy >= 0 && gy < H)
                v = ((const float4*)(hb + gy * W))[i - r * W4];
            ((float4*)u.tile)[i] = v;
        }
    }
    __syncthreads();

    // ---- Fused NMS: vertical 3-max in regs + shuffle horizontal 3-max,
    //      direct per-candidate global scatter (no ballots, no local buffer).
    // TR*W4 = 1600 items: 6 full iters + 64 (2 full warps) -> warp-uniform.
    #pragma unroll
    for (int uu = 0; uu < 7; uu++) {
        int i = tid + uu * 256;
        if (i < TR * W4) {
            int r  = i / W4;
            int c4 = i - r * W4;
            int x0 = c4 * 4;
            const float4 t0 = ((const float4*)u.tile)[(r    ) * W4 + c4];
            const float4 t1 = ((const float4*)u.tile)[(r + 1) * W4 + c4];
            const float4 t2 = ((const float4*)u.tile)[(r + 2) * W4 + c4];
            float4 cm;
            cm.x = fmax3(t0.x, t1.x, t2.x);
            cm.y = fmax3(t0.y, t1.y, t2.y);
            cm.z = fmax3(t0.z, t1.z, t2.z);
            cm.w = fmax3(t0.w, t1.w, t2.w);

            float lf = __shfl_up_sync(0xffffffffu, cm.w, 1);
            float rt = __shfl_down_sync(0xffffffffu, cm.x, 1);
            if (c4 == 0) {
                lf = cm.x;                                   // x = 0 clamp
            } else if (lane == 0) {
                lf = fmax3(u.tile[r * W + x0 - 1],
                           u.tile[(r + 1) * W + x0 - 1],
                           u.tile[(r + 2) * W + x0 - 1]);
            }
            if (c4 == W4 - 1) {
                rt = cm.w;                                   // x = W-1 clamp
            } else if (lane == 31) {
                rt = fmax3(u.tile[r * W + x0 + 4],
                           u.tile[(r + 1) * W + x0 + 4],
                           u.tile[(r + 2) * W + x0 + 4]);
            }

            float wm[4];
            wm[0] = fmax3(lf,   cm.x, cm.y);
            wm[1] = fmax3(cm.x, cm.y, cm.z);
            wm[2] = fmax3(cm.y, cm.z, cm.w);
            wm[3] = fmax3(cm.z, cm.w, rt);
            float mv[4] = {t1.x, t1.y, t1.z, t1.w};

            #pragma unroll
            for (int e = 0; e < 4; e++) {
                if (mv[e] > 0.5f && mv[e] >= wm[e]) {
                    unsigned bits = __float_as_uint(mv[e]);
                    unsigned bin  = binOf(bits);
                    unsigned slot = atomicAdd(&g_binc[b * NBIN + bin], 1u);
                    if (slot < SEGCAP) {
                        unsigned pixIdx = (unsigned)((y0 + r) * W + x0 + e);
                        g_seg[(size_t)(b * NBIN + bin) * SEGCAP + slot] =
                            ((unsigned long long)bits << 32) | (unsigned)(~pixIdx);
                    }
                }
            }
        }
    }

    // ---- Ticket: last finishing block of this batch becomes the selector ----
    __threadfence();                  // release: publish counts + keys
    __syncthreads();
    if (tid == 0) s_ticket = atomicAdd(&g_done[b], 1u);
    __syncthreads();
    if (s_ticket != NBLK - 1) return;
    __threadfence();                  // acquire: see all other blocks' data
    if (tid == 0) g_done[b] = 0u;     // reset for next replay

    // ======================= Selection (one block per batch) ================
    unsigned h;
    {
        unsigned v = atomicExch(&g_binc[b * NBIN + tid], 0u);  // read + reset
        h = v > SEGCAP ? (unsigned)SEGCAP : v;
        s_hist[tid] = h;
    }
    if (tid < K_TOP) { u.sel.valid[tid] = 0; u.sel.y[tid] = 0; u.sel.x[tid] = 0; u.sel.score[tid] = 0.f; }
    if (tid == 0) s_c = 0;
    __syncthreads();

    // inclusive prefix scan over 256 bins (warp shuffles)
    unsigned x = h;
    #pragma unroll
    for (int d = 1; d < 32; d <<= 1) {
        unsigned t = __shfl_up_sync(0xffffffffu, x, d);
        if (lane >= d) x += t;
    }
    if (lane == 31) s_wsum[wid] = x;
    __syncthreads();
    if (tid < 8) {
        unsigned y = s_wsum[tid];
        #pragma unroll
        for (int d = 1; d < 8; d <<= 1) {
            unsigned t = __shfl_up_sync(0xffu, y, d);
            if (tid >= d) y += t;
        }
        s_wsum[tid] = y;
    }
    __syncthreads();
    const unsigned Pinc = x + (wid ? s_wsum[wid - 1] : 0u);
    s_pre[tid] = Pinc;
    __syncthreads();

    const unsigned T = s_pre[NBIN - 1];
    if (T - Pinc + h >= K_TOP) atomicMax(&s_c, tid);    // keys in bins >= tid
    __syncthreads();
    const int c = s_c;
    const unsigned Pc = s_pre[c] - s_hist[c];           // keys in bins < c
    unsigned n = T - Pc;
    if (n > KEYCAP) n = KEYCAP;

    // load only keys from bins >= c (binary search over prefix)
    for (unsigned i = tid; i < n; i += 256) {
        unsigned g = i + Pc;
        int lo = c, hi = NBIN - 1;
        while (lo < hi) {
            int mid = (lo + hi) >> 1;
            if (s_pre[mid] > g) hi = mid; else lo = mid + 1;
        }
        unsigned idx = g - (s_pre[lo] - s_hist[lo]);
        u.sel.keys[i] = __ldcg(&g_seg[(size_t)(b * NBIN + lo) * SEGCAP + idx]);
    }
    __syncthreads();

    // rank by counting (keys unique)
    for (unsigned i = tid; i < n; i += 256) {
        unsigned long long key = u.sel.keys[i];
        unsigned rank = 0;
        for (unsigned j = 0; j < n; j++) rank += (u.sel.keys[j] > key);
        if (rank < K_TOP) {
            unsigned bits = (unsigned)(key >> 32);
            unsigned idx  = ~((unsigned)key);
            int yv = (int)(idx / W);
            int xv = (int)(idx - (unsigned)yv * W);
            u.sel.score[rank] = __uint_as_float(bits);
            u.sel.y[rank] = yv;
            u.sel.x[rank] = xv;
            u.sel.valid[rank] = 1;
        }
    }
    __syncthreads();

    // coors / scores / mask
    if (tid < K_TOP) {
        int v = u.sel.valid[tid];
        int bk = b * K_TOP + tid;
        out[OFF_COORS  + bk * 2 + 0] = (float)u.sel.y[tid];
        out[OFF_COORS  + bk * 2 + 1] = (float)u.sel.x[tid];
        out[OFF_SCORES + bk]         = v ? u.sel.score[tid] : 0.0f;
        out[OFF_MASK   + bk]         = v ? 1.0f : 0.0f;
    }

    // params gather: 1600 float4 per batch, MLP-7
    const float4* pms4 = (const float4*)pms;
    float4*       out4 = (float4*)(out + OFF_PARAMS);
    float4 vals[7];
    #pragma unroll
    for (int uu = 0; uu < 7; uu++) {
        int e = tid + uu * 256;
        vals[uu] = make_float4(0.f, 0.f, 0.f, 0.f);
        if (e < K_TOP * (P / 4)) {
            int k  = e >> 4;
            int cc = e & 15;
            if (u.sel.valid[k]) {
                long long rowOff = ((long long)(b * H + u.sel.y[k]) * W + u.sel.x[k]) * (P / 4);
                vals[uu] = pms4[rowOff + cc];
            }
        }
    }
    #pragma unroll
    for (int uu = 0; uu < 7; uu++) {
        int e = tid + uu * 256;
        if (e < K_TOP * (P / 4)) {
            int k  = e >> 4;
            int cc = e & 15;
            out4[(long long)(b * K_TOP + k) * (P / 4) + cc] = vals[uu];
        }
    }
}

// ---------------------------------------------------------------------------
extern "C" void kernel_launch(void* const* d_in, const int* in_sizes, int n_in,
                              void* d_out, int out_size) {
    const float* hms = (const float*)d_in[0];
    const float* pms = (const float*)d_in[1];
    float* out = (float*)d_out;

    dim3 g(NBLK, B);
    k_fused<<<g, 256>>>(hms, pms, out);
}